// round 7
// baseline (speedup 1.0000x reference)
#include <cuda_runtime.h>
#include <math.h>

// Problem geometry: x, target are [B=8, C=256, H=128, W=128] float32.
#define BB 8
#define CC 256
#define HW (128 * 128)          // 16384 elements per (b,c) plane
#define PLANES (BB * CC)        // 2048
#define GRID (148 * 7)          // 1036: one balanced wave at 7 CTAs/SM
#define RNPC (1.0 / (double)(BB * HW))  // 1/131072, exact power of two

// Per-plane partial raw power sums, transposed for coalesced finalize reads:
// g_part[k][plane], k: 0..4 = x S1..S5, 5..9 = y S1..S5.
// Every slot rewritten every launch -> deterministic.
__device__ double g_part[10][PLANES];

// ---- packed f32x2 helpers (sm_100+: one instr does two fp32 lanes) ----
typedef unsigned long long u64;

__device__ __forceinline__ u64 pack2(float lo, float hi) {
    u64 r;
    asm("mov.b64 %0, {%1, %2};" : "=l"(r) : "f"(lo), "f"(hi));
    return r;
}
__device__ __forceinline__ void unpack2(u64 v, float& lo, float& hi) {
    asm("mov.b64 {%0, %1}, %2;" : "=f"(lo), "=f"(hi) : "l"(v));
}
__device__ __forceinline__ u64 mul2(u64 a, u64 b) {
    u64 d;
    asm("mul.rn.f32x2 %0, %1, %2;" : "=l"(d) : "l"(a), "l"(b));
    return d;
}
__device__ __forceinline__ u64 add2(u64 a, u64 b) {
    u64 d;
    asm("add.rn.f32x2 %0, %1, %2;" : "=l"(d) : "l"(a), "l"(b));
    return d;
}
__device__ __forceinline__ u64 fma2(u64 a, u64 b, u64 c) {
    u64 d;
    asm("fma.rn.f32x2 %0, %1, %2, %3;" : "=l"(d) : "l"(a), "l"(b), "l"(c));
    return d;
}

// Accumulate packed pair p = (x_elem, y_elem): lanes evolve independently,
// bitwise identical to the scalar version per lane. 7 packed fp ops per 2 floats.
#define ACC5P(p, s1, s2, s3, s4, s5)   \
    do {                               \
        u64 _v2 = mul2((p), (p));      \
        u64 _v3 = mul2(_v2, (p));      \
        s1 = add2(s1, (p));            \
        s2 = add2(s2, _v2);            \
        s3 = add2(s3, _v3);            \
        s4 = fma2(_v2, _v2, s4);       \
        s5 = fma2(_v3, _v2, s5);       \
    } while (0)

__global__ __launch_bounds__(256, 7) void moments_kernel(const float* __restrict__ x,
                                                         const float* __restrict__ y) {
    const int tid = threadIdx.x;    // 256 threads
    const int lane = tid & 31;
    const int warp = tid >> 5;

    __shared__ double red[8][10];

    for (int plane = blockIdx.x; plane < PLANES; plane += GRID) {
        const float4* __restrict__ px =
            reinterpret_cast<const float4*>(x + (size_t)plane * HW);
        const float4* __restrict__ py =
            reinterpret_cast<const float4*>(y + (size_t)plane * HW);

        u64 s1 = 0, s2 = 0, s3 = 0, s4 = 0, s5 = 0;  // packed (x,y) accumulators

#pragma unroll 2
        for (int j = 0; j < (HW / 4) / 256; j++) {   // 16 iterations
            float4 vx = __ldcs(&px[tid + j * 256]);  // streaming: no reuse
            float4 vy = __ldcs(&py[tid + j * 256]);
            u64 p0 = pack2(vx.x, vy.x);
            u64 p1 = pack2(vx.y, vy.y);
            u64 p2 = pack2(vx.z, vy.z);
            u64 p3 = pack2(vx.w, vy.w);
            ACC5P(p0, s1, s2, s3, s4, s5);
            ACC5P(p1, s1, s2, s3, s4, s5);
            ACC5P(p2, s1, s2, s3, s4, s5);
            ACC5P(p3, s1, s2, s3, s4, s5);
        }

        // Unpack to 10 scalars, warp reduce.
        float sx1, sx2, sx3, sx4, sx5, sy1, sy2, sy3, sy4, sy5;
        unpack2(s1, sx1, sy1);
        unpack2(s2, sx2, sy2);
        unpack2(s3, sx3, sy3);
        unpack2(s4, sx4, sy4);
        unpack2(s5, sx5, sy5);

#pragma unroll
        for (int off = 16; off > 0; off >>= 1) {
            sx1 += __shfl_xor_sync(0xFFFFFFFFu, sx1, off);
            sx2 += __shfl_xor_sync(0xFFFFFFFFu, sx2, off);
            sx3 += __shfl_xor_sync(0xFFFFFFFFu, sx3, off);
            sx4 += __shfl_xor_sync(0xFFFFFFFFu, sx4, off);
            sx5 += __shfl_xor_sync(0xFFFFFFFFu, sx5, off);
            sy1 += __shfl_xor_sync(0xFFFFFFFFu, sy1, off);
            sy2 += __shfl_xor_sync(0xFFFFFFFFu, sy2, off);
            sy3 += __shfl_xor_sync(0xFFFFFFFFu, sy3, off);
            sy4 += __shfl_xor_sync(0xFFFFFFFFu, sy4, off);
            sy5 += __shfl_xor_sync(0xFFFFFFFFu, sy5, off);
        }

        if (lane == 0) {
            red[warp][0] = (double)sx1;
            red[warp][1] = (double)sx2;
            red[warp][2] = (double)sx3;
            red[warp][3] = (double)sx4;
            red[warp][4] = (double)sx5;
            red[warp][5] = (double)sy1;
            red[warp][6] = (double)sy2;
            red[warp][7] = (double)sy3;
            red[warp][8] = (double)sy4;
            red[warp][9] = (double)sy5;
        }
        __syncthreads();
        if (tid < 10) {
            double t = 0.0;
#pragma unroll
            for (int w = 0; w < 8; w++) t += red[w][tid];
            g_part[tid][plane] = t;
        }
        __syncthreads();   // red[][] reusable next plane iteration
    }
}

// One block, 256 threads: thread c handles channel c. No atomics, no DDIV.
__global__ __launch_bounds__(256) void finalize_kernel(float* __restrict__ out) {
    const int c = threadIdx.x;

    double s[10];
#pragma unroll
    for (int k = 0; k < 10; k++) {
        double t0 = 0.0, t1 = 0.0;
#pragma unroll
        for (int b = 0; b < BB; b += 2) {
            t0 += g_part[k][b * CC + c];
            t1 += g_part[k][(b + 1) * CC + c];
        }
        s[k] = t0 + t1;
    }

    // Raw moments -> central moments (binomial). RNPC = exact 2^-17.
    double q[5];
    {
        const double mux = s[0] * RNPC, M2x = s[1] * RNPC, M3x = s[2] * RNPC,
                     M4x = s[3] * RNPC, M5x = s[4] * RNPC;
        const double muy = s[5] * RNPC, M2y = s[6] * RNPC, M3y = s[7] * RNPC,
                     M4y = s[8] * RNPC, M5y = s[9] * RNPC;
        const double mux2 = mux * mux, mux3 = mux2 * mux;
        const double muy2 = muy * muy, muy3 = muy2 * muy;

        double m2x = M2x - mux2;
        double m3x = M3x - 3.0 * mux * M2x + 2.0 * mux3;
        double m4x = M4x - 4.0 * mux * M3x + 6.0 * mux2 * M2x - 3.0 * mux2 * mux2;
        double m5x = M5x - 5.0 * mux * M4x + 10.0 * mux2 * M3x - 10.0 * mux3 * M2x +
                     4.0 * mux3 * mux2;

        double m2y = M2y - muy2;
        double m3y = M3y - 3.0 * muy * M2y + 2.0 * muy3;
        double m4y = M4y - 4.0 * muy * M3y + 6.0 * muy2 * M2y - 3.0 * muy2 * muy2;
        double m5y = M5y - 5.0 * muy * M4y + 10.0 * muy2 * M3y - 10.0 * muy3 * M2y +
                     4.0 * muy3 * muy2;

        double d0 = mux - muy;
        double d1 = m2x - m2y;
        double d2 = m3x - m3y;
        double d3 = m4x - m4y;
        double d4 = m5x - m5y;
        q[0] = d0 * d0;
        q[1] = d1 * d1;
        q[2] = d2 * d2;
        q[3] = d3 * d3;
        q[4] = d4 * d4;
    }

#pragma unroll
    for (int off = 16; off > 0; off >>= 1) {
#pragma unroll
        for (int k = 0; k < 5; k++)
            q[k] += __shfl_xor_sync(0xFFFFFFFFu, q[k], off);
    }

    __shared__ double red[8][5];
    const int lane = c & 31;
    const int warp = c >> 5;
    if (lane == 0) {
#pragma unroll
        for (int k = 0; k < 5; k++) red[warp][k] = q[k];
    }
    __syncthreads();

    if (c == 0) {
        double loss = 0.0;
#pragma unroll
        for (int k = 0; k < 5; k++) {
            double t = 0.0;
#pragma unroll
            for (int w = 0; w < 8; w++) t += red[w][k];
            loss += sqrt(t);
        }
        out[0] = (float)loss;
    }
}

extern "C" void kernel_launch(void* const* d_in, const int* in_sizes, int n_in,
                              void* d_out, int out_size) {
    const float* x = (const float*)d_in[0];
    const float* y = (const float*)d_in[1];
    float* out = (float*)d_out;
    (void)in_sizes; (void)n_in; (void)out_size;

    moments_kernel<<<GRID, 256>>>(x, y);
    finalize_kernel<<<1, 256>>>(out);
}